// round 13
// baseline (speedup 1.0000x reference)
#include <cuda_runtime.h>
#include <cuda_bf16.h>
#include <cuda_fp16.h>
#include <cstdint>

#define MPIX   32768
#define CIN    256
#define DV     128
#define NSEQ   4096

// Scratch (allocation-free: __device__ globals)
__device__ __align__(16) __nv_bfloat16 g_xh[MPIX * 256];      // x hi
__device__ __align__(16) __nv_bfloat16 g_xl[MPIX * 256];      // x lo
__device__ __align__(16) __nv_bfloat16 g_wt_h[192 * 256];     // [Wq|Wk|Wv]^T hi [n][k]
__device__ __align__(16) __nv_bfloat16 g_wt_l[192 * 256];
__device__ __align__(16) __nv_bfloat16 g_wot_h[256 * 128];    // Wo^T hi [n][k]
__device__ __align__(16) __nv_bfloat16 g_wot_l[256 * 128];
__device__ __align__(16) __nv_bfloat16 g_qhl[MPIX * 64];      // [qhi 32 | qlo 32]
__device__ __align__(16) __nv_bfloat16 g_khl[MPIX * 64];      // [khi 32 | klo 32]
__device__ __align__(16) __half        g_vt[8 * 128 * 4096];  // V^T fp16 [b][ch][pos]

// ============================ helpers ======================================
__device__ __forceinline__ uint32_t smem_u32(const void* p) {
    uint32_t a;
    asm("{ .reg .u64 t; cvta.to.shared.u64 t, %1; cvt.u32.u64 %0, t; }"
        : "=r"(a) : "l"(p));
    return a;
}
__device__ __forceinline__ void cpa16(uint32_t d, const void* s) {
    asm volatile("cp.async.cg.shared.global [%0], [%1], 16;" :: "r"(d), "l"(s));
}
__device__ __forceinline__ void cpa_commit() {
    asm volatile("cp.async.commit_group;" ::: "memory");
}
__device__ __forceinline__ void cpa_wait0() {
    asm volatile("cp.async.wait_group 0;" ::: "memory");
}
__device__ __forceinline__ void ldsm4(uint32_t& r0, uint32_t& r1,
                                      uint32_t& r2, uint32_t& r3, uint32_t a) {
    asm volatile("ldmatrix.sync.aligned.m8n8.x4.shared.b16 {%0,%1,%2,%3}, [%4];"
                 : "=r"(r0), "=r"(r1), "=r"(r2), "=r"(r3) : "r"(a));
}
__device__ __forceinline__ void mma16816(float d[4], const uint32_t a[4],
                                         uint32_t b0, uint32_t b1) {
    asm volatile("mma.sync.aligned.m16n8k16.row.col.f32.bf16.bf16.f32 "
                 "{%0,%1,%2,%3}, {%4,%5,%6,%7}, {%8,%9}, {%0,%1,%2,%3};"
                 : "+f"(d[0]), "+f"(d[1]), "+f"(d[2]), "+f"(d[3])
                 : "r"(a[0]), "r"(a[1]), "r"(a[2]), "r"(a[3]), "r"(b0), "r"(b1));
}
__device__ __forceinline__ void mma16816h(float d[4], const uint32_t a[4],
                                          uint32_t b0, uint32_t b1) {
    asm volatile("mma.sync.aligned.m16n8k16.row.col.f32.f16.f16.f32 "
                 "{%0,%1,%2,%3}, {%4,%5,%6,%7}, {%8,%9}, {%0,%1,%2,%3};"
                 : "+f"(d[0]), "+f"(d[1]), "+f"(d[2]), "+f"(d[3])
                 : "r"(a[0]), "r"(a[1]), "r"(a[2]), "r"(a[3]), "r"(b0), "r"(b1));
}
__device__ __forceinline__ uint32_t pack_bf(float lo, float hi) {
    uint32_t r;
    asm("cvt.rn.satfinite.bf16x2.f32 %0, %1, %2;" : "=r"(r) : "f"(hi), "f"(lo));
    return r;
}
__device__ __forceinline__ uint32_t pack_hf(float lo, float hi) {
    __half2 h = __floats2half2_rn(lo, hi);   // .x = lo, .y = hi
    return *(uint32_t*)&h;
}
__device__ __forceinline__ float ex2f(float x) {
    float r;
    asm("ex2.approx.f32 %0, %1;" : "=f"(r) : "f"(x));
    return r;
}
__device__ __forceinline__ uint32_t ex2h2(uint32_t x) {
    uint32_t r;
    asm("ex2.approx.f16x2 %0, %1;" : "=r"(r) : "r"(x));
    return r;
}
// swizzled smem addressing
__device__ __forceinline__ uint32_t sw64(uint32_t base, int r, int c) {
    return base + r * 64 + (((uint32_t)c ^ ((r >> 1) & 3)) << 4);
}
__device__ __forceinline__ uint32_t sw128(uint32_t base, int r, int c) {
    return base + r * 128 + (((uint32_t)c ^ (r & 7)) << 4);
}
__device__ __forceinline__ uint32_t sw256(uint32_t base, int r, int c) {
    return base + r * 256 + (((uint32_t)c ^ (r & 7)) << 4);
}

#define L2E 1.44269504f

// ---------------------------------------------------------------------------
// prep_wx: fused weight split/transpose + x split (one launch).
// ---------------------------------------------------------------------------
__global__ __launch_bounds__(256) void prep_wx(
    const float* __restrict__ Wq, const float* __restrict__ Wk,
    const float* __restrict__ Wv, const float* __restrict__ Wo,
    const float* __restrict__ x)
{
    const int bid = blockIdx.x, tid = threadIdx.x;
    if (bid < 192) {
        const int n = bid, k = tid;
        float w;
        if (n < 32)      w = Wq[k * 32 + n];
        else if (n < 64) w = Wk[k * 32 + (n - 32)];
        else             w = Wv[k * 128 + (n - 64)];
        __nv_bfloat16 h = __float2bfloat16(w);
        g_wt_h[n * 256 + k] = h;
        g_wt_l[n * 256 + k] = __float2bfloat16(w - __bfloat162float(h));
    } else if (bid < 448) {
        if (tid < 128) {
            const int n = bid - 192, k = tid;
            float w = Wo[k * 256 + n];
            __nv_bfloat16 h = __float2bfloat16(w);
            g_wot_h[n * 128 + k] = h;
            g_wot_l[n * 128 + k] = __float2bfloat16(w - __bfloat162float(h));
        }
    } else {
        const int i4 = (bid - 448) * 256 + tid;
        float4 v = *(const float4*)(x + (size_t)i4 * 4);
        uint32_t h0 = pack_bf(v.x, v.y), h1 = pack_bf(v.z, v.w);
        float a = v.x - __uint_as_float(h0 << 16);
        float b = v.y - __uint_as_float(h0 & 0xFFFF0000u);
        float c = v.z - __uint_as_float(h1 << 16);
        float d = v.w - __uint_as_float(h1 & 0xFFFF0000u);
        ((uint2*)g_xh)[i4] = make_uint2(h0, h1);
        ((uint2*)g_xl)[i4] = make_uint2(pack_bf(a, b), pack_bf(c, d));
    }
}

// ---------------------------------------------------------------------------
// proj_hmma: qkv = x @ [Wq|Wk|Wv] + bias via split-bf16 HMMA.
// ---------------------------------------------------------------------------
#define PJ_AH(bf) ((bf) * 40960)
#define PJ_AL(bf) (PJ_AH(bf) + 8192)
#define PJ_BH(bf) (PJ_AH(bf) + 16384)
#define PJ_BL(bf) (PJ_AH(bf) + 28672)
#define PJ_SMEM   81920

__device__ __forceinline__ void proj_load(uint32_t sb, int buf, int gm0, int k0, int tid)
{
    #pragma unroll
    for (int p = 0; p < 2; p++) {
        int idx = p * 256 + tid;
        int r = idx >> 2, c = idx & 3;
        cpa16(sw64(sb + PJ_AH(buf), r, c), g_xh + (size_t)(gm0 + r) * 256 + k0 + c * 8);
        cpa16(sw64(sb + PJ_AL(buf), r, c), g_xl + (size_t)(gm0 + r) * 256 + k0 + c * 8);
    }
    #pragma unroll
    for (int p = 0; p < 3; p++) {
        int idx = p * 256 + tid;
        int r = idx >> 2, c = idx & 3;
        cpa16(sw64(sb + PJ_BH(buf), r, c), g_wt_h + (size_t)r * 256 + k0 + c * 8);
        cpa16(sw64(sb + PJ_BL(buf), r, c), g_wt_l + (size_t)r * 256 + k0 + c * 8);
    }
}

__global__ __launch_bounds__(256) void proj_hmma(
    const float* __restrict__ bq, const float* __restrict__ bk,
    const float* __restrict__ bv)
{
    extern __shared__ char smc[];
    const uint32_t sb = smem_u32(smc);
    const int tid = threadIdx.x, warp = tid >> 5, lane = tid & 31;
    const int gm0 = blockIdx.x * 128;
    const int r0 = warp * 16;

    proj_load(sb, 0, gm0, 0, tid);
    cpa_commit(); cpa_wait0(); __syncthreads();

    const int arow = r0 + (lane & 7) + ((lane & 8) ? 8 : 0);
    const int asel = (lane & 16) ? 1 : 0;
    const int brow = lane & 7, bsel = lane >> 3;

    float acc[24][4];
    #pragma unroll
    for (int j = 0; j < 24; j++)
        #pragma unroll
        for (int q = 0; q < 4; q++) acc[j][q] = 0.f;

    for (int s = 0; s < 8; s++) {
        const int cur = s & 1;
        if (s + 1 < 8) { proj_load(sb, cur ^ 1, gm0, (s + 1) * 32, tid); cpa_commit(); }

        uint32_t ah[2][4], al[2][4];
        #pragma unroll
        for (int kc = 0; kc < 2; kc++) {
            ldsm4(ah[kc][0], ah[kc][1], ah[kc][2], ah[kc][3],
                  sw64(sb + PJ_AH(cur), arow, kc * 2 + asel));
            ldsm4(al[kc][0], al[kc][1], al[kc][2], al[kc][3],
                  sw64(sb + PJ_AL(cur), arow, kc * 2 + asel));
        }
        #pragma unroll
        for (int j = 0; j < 24; j++) {
            uint32_t bh[4], bl[4];
            ldsm4(bh[0], bh[1], bh[2], bh[3], sw64(sb + PJ_BH(cur), j * 8 + brow, bsel));
            ldsm4(bl[0], bl[1], bl[2], bl[3], sw64(sb + PJ_BL(cur), j * 8 + brow, bsel));
            mma16816(acc[j], ah[0], bh[0], bh[1]);
            mma16816(acc[j], ah[1], bh[2], bh[3]);
            mma16816(acc[j], al[0], bh[0], bh[1]);
            mma16816(acc[j], al[1], bh[2], bh[3]);
            mma16816(acc[j], ah[0], bl[0], bl[1]);
            mma16816(acc[j], ah[1], bl[2], bl[3]);
        }
        if (s + 1 < 8) { cpa_wait0(); __syncthreads(); }
    }
    __syncthreads();   // before smem reuse

    const int g = lane >> 2, c2 = (lane & 3) * 2;
    // ---- q/k: bias, split, direct store ----
    #pragma unroll
    for (int j = 0; j < 8; j++) {
        const int col = j * 8 + c2;
        float b0, b1;
        __nv_bfloat16* base;
        int cc;
        if (col < 32) { b0 = bq[col]; b1 = bq[col + 1]; base = g_qhl; cc = col; }
        else          { b0 = bk[col - 32]; b1 = bk[col - 31]; base = g_khl; cc = col - 32; }
        #pragma unroll
        for (int half = 0; half < 2; half++) {
            float v0 = acc[j][half * 2 + 0] + b0;
            float v1 = acc[j][half * 2 + 1] + b1;
            uint32_t hp = pack_bf(v0, v1);
            float d0 = v0 - __uint_as_float(hp << 16);
            float d1 = v1 - __uint_as_float(hp & 0xFFFF0000u);
            __nv_bfloat16* ptr = base + (size_t)(gm0 + r0 + g + half * 8) * 64 + cc;
            *(uint32_t*)ptr        = hp;
            *(uint32_t*)(ptr + 32) = pack_bf(d0, d1);
        }
    }
    // ---- v: bias + stage f32, then transpose + fp16 out ----
    float* vst = (float*)smc;                       // [128][132]
    #pragma unroll
    for (int j = 8; j < 24; j++) {
        const int ch = (j - 8) * 8 + c2;
        float b0 = bv[ch], b1 = bv[ch + 1];
        vst[(r0 + g) * 132 + ch]         = acc[j][0] + b0;
        vst[(r0 + g) * 132 + ch + 1]     = acc[j][1] + b1;
        vst[(r0 + g + 8) * 132 + ch]     = acc[j][2] + b0;
        vst[(r0 + g + 8) * 132 + ch + 1] = acc[j][3] + b1;
    }
    __syncthreads();
    const int bb = gm0 >> 12, pos0 = gm0 & 4095;
    #pragma unroll
    for (int it = 0; it < 16; it++) {
        int idx = it * 256 + tid;
        int ch = idx >> 5, p4 = (idx & 31) * 4;
        float v0 = vst[(p4 + 0) * 132 + ch];
        float v1 = vst[(p4 + 1) * 132 + ch];
        float v2 = vst[(p4 + 2) * 132 + ch];
        float v3 = vst[(p4 + 3) * 132 + ch];
        size_t dst = ((size_t)bb * 128 + ch) * 4096 + pos0 + p4;
        *(uint2*)(g_vt + dst) = make_uint2(pack_hf(v0, v1), pack_hf(v2, v3));
    }
}

// ---------------------------------------------------------------------------
// attn: HMMA flash attention + fused output projection.
// 256 q-rows/CTA (8 warps x 32 rows in 2 groups of 16), grid = 128.
// K/V fragments shared across both row groups -> smem traffic per work halved.
// Epilogue processes row groups SEQUENTIALLY to keep register peak flat.
// smem: Q[32K] | buf{K 16K, V 32K} x2 = 128 KB
// ---------------------------------------------------------------------------
#define SM_Q      0
#define SM_K(bf)  (32768 + (bf) * 49152)
#define SM_V(bf)  (SM_K(bf) + 16384)
#define SM_TOTAL  (32768 + 2 * 49152)
// epilogue B buffers reuse freed KV smem (safe after post-loop syncthreads)
#define EB(bf)    (32768 + (bf) * 32768)     // each: hi 8KB | lo 8KB (16KB used)

__device__ __forceinline__ void issue_kv(uint32_t sb, int bf, int b, int j0, int tid)
{
    const uint32_t kb = sb + SM_K(bf), vb = sb + SM_V(bf);
    #pragma unroll
    for (int p = 0; p < 4; p++) {
        int idx = p * 256 + tid;
        int r = idx >> 3, c = idx & 7;
        cpa16(sw128(kb, r, c), g_khl + ((size_t)(b * 4096 + j0 + r)) * 64 + c * 8);
    }
    #pragma unroll
    for (int p = 0; p < 8; p++) {
        int idx = p * 256 + tid;
        int r = idx >> 4, c = idx & 15;
        cpa16(sw256(vb, r, c), g_vt + ((size_t)(b * 128 + r)) * 4096 + j0 + c * 8);
    }
}

__device__ __forceinline__ void issue_B(uint32_t sb, int bf, int nh, int ks, int tid)
{
    const uint32_t bh = sb + EB(bf), bl = sb + EB(bf) + 8192;
    #pragma unroll
    for (int p = 0; p < 2; p++) {
        int idx = p * 256 + tid;
        int r = idx >> 2, c = idx & 3;
        const size_t src = (size_t)(nh * 128 + r) * 128 + ks * 32 + c * 8;
        cpa16(sw64(bh, r, c), g_wot_h + src);
        cpa16(sw64(bl, r, c), g_wot_l + src);
    }
}

__device__ __forceinline__ void softmax_chunk(
    const float s[4][4], float& m0, float& m1,
    float& corr0, float& corr1, uint32_t pf[2][4])
{
    float cm0 = -1e30f, cm1 = -1e30f;
    #pragma unroll
    for (int jj = 0; jj < 4; jj++) {
        cm0 = fmaxf(cm0, fmaxf(s[jj][0], s[jj][1]));
        cm1 = fmaxf(cm1, fmaxf(s[jj][2], s[jj][3]));
    }
    cm0 = fmaxf(cm0, __shfl_xor_sync(0xffffffffu, cm0, 1));
    cm0 = fmaxf(cm0, __shfl_xor_sync(0xffffffffu, cm0, 2));
    cm1 = fmaxf(cm1, __shfl_xor_sync(0xffffffffu, cm1, 1));
    cm1 = fmaxf(cm1, __shfl_xor_sync(0xffffffffu, cm1, 2));
    const float mn0 = fmaxf(m0, cm0), mn1 = fmaxf(m1, cm1);
    corr0 = ex2f((m0 - mn0) * L2E);
    corr1 = ex2f((m1 - mn1) * L2E);
    m0 = mn0; m1 = mn1;
    const float sh0 = mn0 * L2E, sh1 = mn1 * L2E;
    #pragma unroll
    for (int jj = 0; jj < 4; jj++) {
        float x0 = fmaf(s[jj][0], L2E, -sh0);
        float x1 = fmaf(s[jj][1], L2E, -sh0);
        float x2 = fmaf(s[jj][2], L2E, -sh1);
        float x3 = fmaf(s[jj][3], L2E, -sh1);
        pf[jj >> 1][(jj & 1) * 2 + 0] = ex2h2(pack_hf(x0, x1));
        pf[jj >> 1][(jj & 1) * 2 + 1] = ex2h2(pack_hf(x2, x3));
    }
}

__global__ __launch_bounds__(256, 1) void attn_kernel(
    const float* __restrict__ x, const float* __restrict__ bo,
    float* __restrict__ out)
{
    extern __shared__ char smc[];
    const uint32_t sb = smem_u32(smc);
    const int tid  = threadIdx.x;
    const int warp = tid >> 5;
    const int lane = tid & 31;
    const int b  = blockIdx.x >> 4;
    const int mt = blockIdx.x & 15;
    const size_t qrow0 = (size_t)b * 4096 + (size_t)mt * 256;
    const int r0 = warp * 32;

    // Q tile: 256 rows
    #pragma unroll
    for (int p = 0; p < 8; p++) {
        int idx = p * 256 + tid;
        int r = idx >> 3, c = idx & 7;
        cpa16(sw128(sb + SM_Q, r, c), g_qhl + (qrow0 + r) * 64 + c * 8);
    }
    issue_kv(sb, 0, b, 0, tid);
    cpa_commit(); cpa_wait0(); __syncthreads();

    const int asel = (lane & 16) ? 1 : 0;
    uint32_t qh[2][2][4], ql[2][2][4];      // [group][kchunk][4]
    #pragma unroll
    for (int gr = 0; gr < 2; gr++) {
        const int arow = r0 + gr * 16 + (lane & 7) + ((lane & 8) ? 8 : 0);
        #pragma unroll
        for (int kc = 0; kc < 2; kc++) {
            ldsm4(qh[gr][kc][0], qh[gr][kc][1], qh[gr][kc][2], qh[gr][kc][3],
                  sw128(sb + SM_Q, arow, kc * 2 + asel));
            ldsm4(ql[gr][kc][0], ql[gr][kc][1], ql[gr][kc][2], ql[gr][kc][3],
                  sw128(sb + SM_Q, arow, 4 + kc * 2 + asel));
        }
    }

    float o0[16][4], o1[16][4];
    #pragma unroll
    for (int j = 0; j < 16; j++)
        #pragma unroll
        for (int q = 0; q < 4; q++) { o0[j][q] = 0.f; o1[j][q] = 0.f; }
    float o16[2][4] = {{0.f,0.f,0.f,0.f},{0.f,0.f,0.f,0.f}};
    float m00 = -1e30f, m01 = -1e30f, m10 = -1e30f, m11 = -1e30f;

    const uint32_t bones = (lane < 4) ? pack_hf(1.f, 1.f) : 0u;
    const int brow = lane & 7;
    const int bsel = lane >> 3;

    for (int i = 0; i < 32; i++) {
        const int cur = i & 1;
        if (i + 1 < 32) { issue_kv(sb, cur ^ 1, b, (i + 1) * 128, tid); cpa_commit(); }

        const uint32_t kb = sb + SM_K(cur);
        const uint32_t vbuf = sb + SM_V(cur);

        #pragma unroll
        for (int c2k = 0; c2k < 4; c2k++) {
            // ---- S for both row groups; K fragments shared ----
            float s0[4][4], s1[4][4];
            #pragma unroll
            for (int jj = 0; jj < 4; jj++) {
                const int jt = c2k * 4 + jj;
                #pragma unroll
                for (int q = 0; q < 4; q++) { s0[jj][q] = 0.f; s1[jj][q] = 0.f; }
                uint32_t kr[4], kl[4];
                ldsm4(kr[0], kr[1], kr[2], kr[3], sw128(kb, jt * 8 + brow, bsel));
                ldsm4(kl[0], kl[1], kl[2], kl[3], sw128(kb, jt * 8 + brow, 4 + bsel));
                mma16816(s0[jj], qh[0][0], kr[0], kr[1]);
                mma16816(s0[jj], qh[0][1], kr[2], kr[3]);
                mma16816(s0[jj], ql[0][0], kr[0], kr[1]);
                mma16816(s0[jj], ql[0][1], kr[2], kr[3]);
                mma16816(s0[jj], qh[0][0], kl[0], kl[1]);
                mma16816(s0[jj], qh[0][1], kl[2], kl[3]);
                mma16816(s1[jj], qh[1][0], kr[0], kr[1]);
                mma16816(s1[jj], qh[1][1], kr[2], kr[3]);
                mma16816(s1[jj], ql[1][0], kr[0], kr[1]);
                mma16816(s1[jj], ql[1][1], kr[2], kr[3]);
                mma16816(s1[jj], qh[1][0], kl[0], kl[1]);
                mma16816(s1[jj], qh[1][1], kl[2], kl[3]);
            }
            // ---- softmax both groups ----
            uint32_t pf0[2][4], pf1[2][4];
            float c00, c01, c10, c11;
            softmax_chunk(s0, m00, m01, c00, c01, pf0);
            softmax_chunk(s1, m10, m11, c10, c11, pf1);
            if (__any_sync(0xffffffffu,
                    (c00 < 1.f) || (c01 < 1.f) || (c10 < 1.f) || (c11 < 1.f))) {
                #pragma unroll
                for (int j = 0; j < 16; j++) {
                    o0[j][0] *= c00; o0[j][1] *= c00;
                    o0[j][2] *= c01; o0[j][3] *= c01;
                    o1[j][0] *= c10; o1[j][1] *= c10;
                    o1[j][2] *= c11; o1[j][3] *= c11;
                }
                o16[0][0] *= c00; o16[0][1] *= c00;
                o16[0][2] *= c01; o16[0][3] *= c01;
                o16[1][0] *= c10; o16[1][1] *= c10;
                o16[1][2] *= c11; o16[1][3] *= c11;
            }
            // ---- PV: one V fragment feeds both groups ----
            #pragma unroll
            for (int j = 0; j < 16; j++) {
                uint32_t vb[4];
                ldsm4(vb[0], vb[1], vb[2], vb[3], sw256(vbuf, j * 8 + brow, c2k * 4 + bsel));
                mma16816h(o0[j], pf0[0], vb[0], vb[1]);
                mma16816h(o0[j], pf0[1], vb[2], vb[3]);
                mma16816h(o1[j], pf1[0], vb[0], vb[1]);
                mma16816h(o1[j], pf1[1], vb[2], vb[3]);
            }
            mma16816h(o16[0], pf0[0], bones, bones);
            mma16816h(o16[0], pf0[1], bones, bones);
            mma16816h(o16[1], pf1[0], bones, bones);
            mma16816h(o16[1], pf1[1], bones, bones);
        }
        if (i + 1 < 32) { cpa_wait0(); __syncthreads(); }
    }

    // ================= fused output projection (sequential groups) ========
    const float l00 = __shfl_sync(0xffffffffu, o16[0][0], lane & 0x1C);
    const float l01 = __shfl_sync(0xffffffffu, o16[0][2], lane & 0x1C);
    const float l10 = __shfl_sync(0xffffffffu, o16[1][0], lane & 0x1C);
    const float l11 = __shfl_sync(0xffffffffu, o16[1][2], lane & 0x1C);

    // start first Wo chunk load (EB(0) disjoint from last-used K(1)/V(1))
    issue_B(sb, 0, 0, 0, tid);
    cpa_commit();

    const int g = lane >> 2, c2 = (lane & 3) * 2;
    int buf = 0;
    #pragma unroll
    for (int gr = 0; gr < 2; gr++) {
        // pack THIS group's O into split-bf16 A fragments (group's o dies here)
        const float li0 = 1.f / (gr ? l10 : l00);
        const float li1 = 1.f / (gr ? l11 : l01);
        float (*ov)[4] = gr ? o1 : o0;
        uint32_t ahf[8][4], alf[8][4];
        #pragma unroll
        for (int kc = 0; kc < 8; kc++) {
            const int j0 = 2 * kc, j1 = 2 * kc + 1;
            float a00 = ov[j0][0] * li0, a01 = ov[j0][1] * li0;
            float a02 = ov[j0][2] * li1, a03 = ov[j0][3] * li1;
            float a10 = ov[j1][0] * li0, a11 = ov[j1][1] * li0;
            float a12 = ov[j1][2] * li1, a13 = ov[j1][3] * li1;
            uint32_t h0 = pack_bf(a00, a01), h1 = pack_bf(a02, a03);
            uint32_t h2 = pack_bf(a10, a11), h3 = pack_bf(a12, a13);
            ahf[kc][0] = h0; ahf[kc][1] = h1; ahf[kc][2] = h2; ahf[kc][3] = h3;
            alf[kc][0] = pack_bf(a00 - __uint_as_float(h0 << 16),
                                 a01 - __uint_as_float(h0 & 0xFFFF0000u));
            alf[kc][1] = pack_bf(a02 - __uint_as_float(h1 << 16),
                                 a03 - __uint_as_float(h1 & 0xFFFF0000u));
            alf[kc][2] = pack_bf(a10 - __uint_as_float(h2 << 16),
                                 a11 - __uint_as_float(h2 & 0xFFFF0000u));
            alf[kc][3] = pack_bf(a12 - __uint_as_float(h3 << 16),
                                 a13 - __uint_as_float(h3 & 0xFFFF0000u));
        }

        #pragma unroll
        for (int nh = 0; nh < 2; nh++) {
            float acc[16][4];
            #pragma unroll
            for (int j = 0; j < 16; j++)
                #pragma unroll
                for (int q = 0; q < 4; q++) acc[j][q] = 0.f;

            #pragma unroll
            for (int ks = 0; ks < 4; ks++) {
                cpa_wait0(); __syncthreads();
                const int nstep = gr * 8 + nh * 4 + ks + 1;
                if (nstep < 16) {
                    const int ns = nstep & 7;
                    issue_B(sb, buf ^ 1, ns >> 2, ns & 3, tid);
                    cpa_commit();
                }
                const uint32_t bhb = sb + EB(buf), blb = sb + EB(buf) + 8192;
                const uint32_t* a0h = ahf[ks * 2];
                const uint32_t* a1h = ahf[ks * 2 + 1];
                const uint32_t* a0l = alf[ks * 2];
                const uint32_t* a1l = alf[ks * 2 + 1];
                #pragma unroll
                for (int j = 0; j < 16; j++) {
                    uint32_t bh[4], bl[4];
                    ldsm4(bh[0], bh[1], bh[2], bh[3], sw64(bhb, j * 8 + brow, bsel));
                    ldsm4(bl[0], bl[1], bl[2], bl[3], sw64(blb, j * 8 + brow, bsel));
                    mma16816(acc[j], a0h, bh[0], bh[1]);
                    mma16816(acc[j], a1h, bh[2], bh[3]);
                    mma16816(acc[j], a0l, bh[0], bh[1]);
                    mma16816(acc[j], a1l, bh[2], bh[3]);
                    mma16816(acc[j], a0h, bl[0], bl[1]);
                    mma16816(acc[j], a1h, bl[2], bl[3]);
                }
                buf ^= 1;
            }
            // ---- store this (group, n-half): + bo + x ----
            #pragma unroll
            for (int j = 0; j < 16; j++) {
                const int col = nh * 128 + j * 8 + c2;
                const float b0 = bo[col], b1 = bo[col + 1];
                #pragma unroll
                for (int half = 0; half < 2; half++) {
                    const size_t grow = qrow0 + r0 + gr * 16 + g + half * 8;
                    float2 xr = *(const float2*)(x + grow * 256 + col);
                    float2 r;
                    r.x = acc[j][half * 2 + 0] + b0 + xr.x;
                    r.y = acc[j][half * 2 + 1] + b1 + xr.y;
                    *(float2*)(out + grow * 256 + col) = r;
                }
            }
        }
    }
}

// ---------------------------------------------------------------------------
extern "C" void kernel_launch(void* const* d_in, const int* in_sizes, int n_in,
                              void* d_out, int out_size)
{
    const float* x  = (const float*)d_in[0];
    const float* Wq = (const float*)d_in[1];
    const float* bq = (const float*)d_in[2];
    const float* Wk = (const float*)d_in[3];
    const float* bk = (const float*)d_in[4];
    const float* Wv = (const float*)d_in[5];
    const float* bv = (const float*)d_in[6];
    const float* Wo = (const float*)d_in[7];
    const float* bo = (const float*)d_in[8];
    float* out = (float*)d_out;

    cudaFuncSetAttribute(proj_hmma, cudaFuncAttributeMaxDynamicSharedMemorySize, PJ_SMEM);
    cudaFuncSetAttribute(attn_kernel, cudaFuncAttributeMaxDynamicSharedMemorySize, SM_TOTAL);

    prep_wx<<<448 + 8192, 256>>>(Wq, Wk, Wv, Wo, x);
    proj_hmma<<<256, 256, PJ_SMEM>>>(bq, bk, bv);
    attn_kernel<<<128, 256, SM_TOTAL>>>(x, bo, out);
}

// round 14
// speedup vs baseline: 1.1666x; 1.1666x over previous
#include <cuda_runtime.h>
#include <cuda_bf16.h>
#include <cuda_fp16.h>
#include <cstdint>

#define MPIX   32768
#define CIN    256
#define DV     128
#define NSEQ   4096

// Scratch (allocation-free: __device__ globals)
__device__ __align__(16) __nv_bfloat16 g_wt_h[192 * 256];     // [Wq|Wk|Wv]^T hi [n][k]
__device__ __align__(16) __nv_bfloat16 g_wt_l[192 * 256];
__device__ __align__(16) __nv_bfloat16 g_wot_h[256 * 128];    // Wo^T hi [n][k]
__device__ __align__(16) __nv_bfloat16 g_wot_l[256 * 128];
__device__ __align__(16) __nv_bfloat16 g_qhl[MPIX * 64];      // [qhi 32 | qlo 32]
__device__ __align__(16) __nv_bfloat16 g_khl[MPIX * 64];      // [khi 32 | klo 32]
__device__ __align__(16) __half        g_vt[8 * 128 * 4096];  // V^T fp16 [b][ch][pos]

// ============================ helpers ======================================
__device__ __forceinline__ uint32_t smem_u32(const void* p) {
    uint32_t a;
    asm("{ .reg .u64 t; cvta.to.shared.u64 t, %1; cvt.u32.u64 %0, t; }"
        : "=r"(a) : "l"(p));
    return a;
}
__device__ __forceinline__ void cpa16(uint32_t d, const void* s) {
    asm volatile("cp.async.cg.shared.global [%0], [%1], 16;" :: "r"(d), "l"(s));
}
__device__ __forceinline__ void cpa_commit() {
    asm volatile("cp.async.commit_group;" ::: "memory");
}
__device__ __forceinline__ void cpa_wait0() {
    asm volatile("cp.async.wait_group 0;" ::: "memory");
}
__device__ __forceinline__ void ldsm4(uint32_t& r0, uint32_t& r1,
                                      uint32_t& r2, uint32_t& r3, uint32_t a) {
    asm volatile("ldmatrix.sync.aligned.m8n8.x4.shared.b16 {%0,%1,%2,%3}, [%4];"
                 : "=r"(r0), "=r"(r1), "=r"(r2), "=r"(r3) : "r"(a));
}
__device__ __forceinline__ void sts128(uint32_t addr, uint32_t r0, uint32_t r1,
                                       uint32_t r2, uint32_t r3) {
    asm volatile("st.shared.v4.b32 [%0], {%1,%2,%3,%4};"
                 :: "r"(addr), "r"(r0), "r"(r1), "r"(r2), "r"(r3) : "memory");
}
__device__ __forceinline__ void mma16816(float d[4], const uint32_t a[4],
                                         uint32_t b0, uint32_t b1) {
    asm volatile("mma.sync.aligned.m16n8k16.row.col.f32.bf16.bf16.f32 "
                 "{%0,%1,%2,%3}, {%4,%5,%6,%7}, {%8,%9}, {%0,%1,%2,%3};"
                 : "+f"(d[0]), "+f"(d[1]), "+f"(d[2]), "+f"(d[3])
                 : "r"(a[0]), "r"(a[1]), "r"(a[2]), "r"(a[3]), "r"(b0), "r"(b1));
}
__device__ __forceinline__ void mma16816h(float d[4], const uint32_t a[4],
                                          uint32_t b0, uint32_t b1) {
    asm volatile("mma.sync.aligned.m16n8k16.row.col.f32.f16.f16.f32 "
                 "{%0,%1,%2,%3}, {%4,%5,%6,%7}, {%8,%9}, {%0,%1,%2,%3};"
                 : "+f"(d[0]), "+f"(d[1]), "+f"(d[2]), "+f"(d[3])
                 : "r"(a[0]), "r"(a[1]), "r"(a[2]), "r"(a[3]), "r"(b0), "r"(b1));
}
__device__ __forceinline__ uint32_t pack_bf(float lo, float hi) {
    uint32_t r;
    asm("cvt.rn.satfinite.bf16x2.f32 %0, %1, %2;" : "=r"(r) : "f"(hi), "f"(lo));
    return r;
}
__device__ __forceinline__ uint32_t pack_hf(float lo, float hi) {
    __half2 h = __floats2half2_rn(lo, hi);   // .x = lo, .y = hi
    return *(uint32_t*)&h;
}
__device__ __forceinline__ float ex2f(float x) {
    float r;
    asm("ex2.approx.f32 %0, %1;" : "=f"(r) : "f"(x));
    return r;
}
__device__ __forceinline__ uint32_t ex2h2(uint32_t x) {
    uint32_t r;
    asm("ex2.approx.f16x2 %0, %1;" : "=r"(r) : "r"(x));
    return r;
}
// swizzled smem addressing
__device__ __forceinline__ uint32_t sw64(uint32_t base, int r, int c) {
    return base + r * 64 + (((uint32_t)c ^ ((r >> 1) & 3)) << 4);
}
__device__ __forceinline__ uint32_t sw128(uint32_t base, int r, int c) {
    return base + r * 128 + (((uint32_t)c ^ (r & 7)) << 4);
}
__device__ __forceinline__ uint32_t sw256(uint32_t base, int r, int c) {
    return base + r * 256 + (((uint32_t)c ^ (r & 7)) << 4);
}

#define L2E 1.44269504f

// ---------------------------------------------------------------------------
// prep_w: split + transpose weights (tiny).
// ---------------------------------------------------------------------------
__global__ __launch_bounds__(256) void prep_w(
    const float* __restrict__ Wq, const float* __restrict__ Wk,
    const float* __restrict__ Wv, const float* __restrict__ Wo)
{
    const int bid = blockIdx.x, k = threadIdx.x;
    if (bid < 192) {
        const int n = bid;
        float w;
        if (n < 32)      w = Wq[k * 32 + n];
        else if (n < 64) w = Wk[k * 32 + (n - 32)];
        else             w = Wv[k * 128 + (n - 64)];
        __nv_bfloat16 h = __float2bfloat16(w);
        g_wt_h[n * 256 + k] = h;
        g_wt_l[n * 256 + k] = __float2bfloat16(w - __bfloat162float(h));
    } else if (k < 128) {
        const int n = bid - 192;
        float w = Wo[k * 256 + n];
        __nv_bfloat16 h = __float2bfloat16(w);
        g_wot_h[n * 128 + k] = h;
        g_wot_l[n * 128 + k] = __float2bfloat16(w - __bfloat162float(h));
    }
}

// ---------------------------------------------------------------------------
// proj_hmma: qkv = x @ [Wq|Wk|Wv] + bias via split-bf16 HMMA.
// x is loaded as f32 and split to bf16 hi/lo IN-KERNEL (prep_x deleted).
// smem: Ah 8K | Al 8K | B bufs 2 x (Bh 12K + Bl 12K) -> 64K;
//       epilogue reuses smem as f32 [128][132] = 67.6K -> PJ_SMEM 69632.
// ---------------------------------------------------------------------------
#define PJ_A_H    0
#define PJ_A_L    8192
#define PJ_BH(bf) (16384 + (bf) * 24576)
#define PJ_BL(bf) (PJ_BH(bf) + 12288)
#define PJ_SMEM   69632

__device__ __forceinline__ void proj_loadB(uint32_t sb, int buf, int k0, int tid)
{
    #pragma unroll
    for (int p = 0; p < 3; p++) {
        int idx = p * 256 + tid;
        int r = idx >> 2, c = idx & 3;
        cpa16(sw64(sb + PJ_BH(buf), r, c), g_wt_h + (size_t)r * 256 + k0 + c * 8);
        cpa16(sw64(sb + PJ_BL(buf), r, c), g_wt_l + (size_t)r * 256 + k0 + c * 8);
    }
}

__global__ __launch_bounds__(256) void proj_hmma(
    const float* __restrict__ x,
    const float* __restrict__ bq, const float* __restrict__ bk,
    const float* __restrict__ bv)
{
    extern __shared__ char smc[];
    const uint32_t sb = smem_u32(smc);
    const int tid = threadIdx.x, warp = tid >> 5, lane = tid & 31;
    const int gm0 = blockIdx.x * 128;
    const int r0 = warp * 16;

    // this thread's two A chunks: rows xr0, xr0+64, chunk col xc
    const int xr0 = tid >> 2, xc = tid & 3;

    // prefetch x f32 for step 0
    float4 xv[4];
    {
        const float* p0 = x + (size_t)(gm0 + xr0) * 256 + xc * 8;
        const float* p1 = x + (size_t)(gm0 + xr0 + 64) * 256 + xc * 8;
        xv[0] = *(const float4*)p0;       xv[1] = *(const float4*)(p0 + 4);
        xv[2] = *(const float4*)p1;       xv[3] = *(const float4*)(p1 + 4);
    }
    proj_loadB(sb, 0, 0, tid);
    cpa_commit(); cpa_wait0();

    const int arow = r0 + (lane & 7) + ((lane & 8) ? 8 : 0);
    const int asel = (lane & 16) ? 1 : 0;
    const int brow = lane & 7, bsel = lane >> 3;

    float acc[24][4];
    #pragma unroll
    for (int j = 0; j < 24; j++)
        #pragma unroll
        for (int q = 0; q < 4; q++) acc[j][q] = 0.f;

    for (int s = 0; s < 8; s++) {
        const int cur = s & 1;
        // ---- stage A: split xv -> Ah/Al (swizzled) ----
        #pragma unroll
        for (int ch = 0; ch < 2; ch++) {
            const int r = xr0 + ch * 64;
            float f[8] = { xv[2*ch].x, xv[2*ch].y, xv[2*ch].z, xv[2*ch].w,
                           xv[2*ch+1].x, xv[2*ch+1].y, xv[2*ch+1].z, xv[2*ch+1].w };
            uint32_t h[4], l[4];
            #pragma unroll
            for (int q = 0; q < 4; q++) {
                h[q] = pack_bf(f[2*q], f[2*q+1]);
                l[q] = pack_bf(f[2*q]   - __uint_as_float(h[q] << 16),
                               f[2*q+1] - __uint_as_float(h[q] & 0xFFFF0000u));
            }
            sts128(sw64(sb + PJ_A_H, r, xc), h[0], h[1], h[2], h[3]);
            sts128(sw64(sb + PJ_A_L, r, xc), l[0], l[1], l[2], l[3]);
        }
        if (s + 1 < 8) { proj_loadB(sb, cur ^ 1, (s + 1) * 32, tid); cpa_commit(); }
        __syncthreads();                                  // A visible

        uint32_t ah[2][4], al[2][4];
        #pragma unroll
        for (int kc = 0; kc < 2; kc++) {
            ldsm4(ah[kc][0], ah[kc][1], ah[kc][2], ah[kc][3],
                  sw64(sb + PJ_A_H, arow, kc * 2 + asel));
            ldsm4(al[kc][0], al[kc][1], al[kc][2], al[kc][3],
                  sw64(sb + PJ_A_L, arow, kc * 2 + asel));
        }
        __syncthreads();                                  // A consumed -> reusable

        // prefetch x for next step (overlaps MMAs)
        if (s + 1 < 8) {
            const float* p0 = x + (size_t)(gm0 + xr0) * 256 + (s + 1) * 32 + xc * 8;
            const float* p1 = x + (size_t)(gm0 + xr0 + 64) * 256 + (s + 1) * 32 + xc * 8;
            xv[0] = *(const float4*)p0;   xv[1] = *(const float4*)(p0 + 4);
            xv[2] = *(const float4*)p1;   xv[3] = *(const float4*)(p1 + 4);
        }

        #pragma unroll
        for (int j = 0; j < 24; j++) {
            uint32_t bh[4], bl[4];
            ldsm4(bh[0], bh[1], bh[2], bh[3], sw64(sb + PJ_BH(cur), j * 8 + brow, bsel));
            ldsm4(bl[0], bl[1], bl[2], bl[3], sw64(sb + PJ_BL(cur), j * 8 + brow, bsel));
            mma16816(acc[j], ah[0], bh[0], bh[1]);
            mma16816(acc[j], ah[1], bh[2], bh[3]);
            mma16816(acc[j], al[0], bh[0], bh[1]);
            mma16816(acc[j], al[1], bh[2], bh[3]);
            mma16816(acc[j], ah[0], bl[0], bl[1]);
            mma16816(acc[j], ah[1], bl[2], bl[3]);
        }
        if (s + 1 < 8) { cpa_wait0(); }
        __syncthreads();
    }

    const int g = lane >> 2, c2 = (lane & 3) * 2;
    // ---- q/k: bias, split, direct store ----
    #pragma unroll
    for (int j = 0; j < 8; j++) {
        const int col = j * 8 + c2;
        float b0, b1;
        __nv_bfloat16* base;
        int cc;
        if (col < 32) { b0 = bq[col]; b1 = bq[col + 1]; base = g_qhl; cc = col; }
        else          { b0 = bk[col - 32]; b1 = bk[col - 31]; base = g_khl; cc = col - 32; }
        #pragma unroll
        for (int half = 0; half < 2; half++) {
            float v0 = acc[j][half * 2 + 0] + b0;
            float v1 = acc[j][half * 2 + 1] + b1;
            uint32_t hp = pack_bf(v0, v1);
            float d0 = v0 - __uint_as_float(hp << 16);
            float d1 = v1 - __uint_as_float(hp & 0xFFFF0000u);
            __nv_bfloat16* ptr = base + (size_t)(gm0 + r0 + g + half * 8) * 64 + cc;
            *(uint32_t*)ptr        = hp;
            *(uint32_t*)(ptr + 32) = pack_bf(d0, d1);
        }
    }
    // ---- v: bias + stage f32, then transpose + fp16 out ----
    float* vst = (float*)smc;                       // [128][132]
    #pragma unroll
    for (int j = 8; j < 24; j++) {
        const int ch = (j - 8) * 8 + c2;
        float b0 = bv[ch], b1 = bv[ch + 1];
        vst[(r0 + g) * 132 + ch]         = acc[j][0] + b0;
        vst[(r0 + g) * 132 + ch + 1]     = acc[j][1] + b1;
        vst[(r0 + g + 8) * 132 + ch]     = acc[j][2] + b0;
        vst[(r0 + g + 8) * 132 + ch + 1] = acc[j][3] + b1;
    }
    __syncthreads();
    const int bb = gm0 >> 12, pos0 = gm0 & 4095;
    #pragma unroll
    for (int it = 0; it < 16; it++) {
        int idx = it * 256 + tid;
        int ch = idx >> 5, p4 = (idx & 31) * 4;
        float v0 = vst[(p4 + 0) * 132 + ch];
        float v1 = vst[(p4 + 1) * 132 + ch];
        float v2 = vst[(p4 + 2) * 132 + ch];
        float v3 = vst[(p4 + 3) * 132 + ch];
        size_t dst = ((size_t)bb * 128 + ch) * 4096 + pos0 + p4;
        *(uint2*)(g_vt + dst) = make_uint2(pack_hf(v0, v1), pack_hf(v2, v3));
    }
}

// ---------------------------------------------------------------------------
// attn: HMMA flash attention + fused output projection (R11 design).
// 128 q-rows/CTA, 8 warps x 16 rows, grid 256, 1 CTA/SM.
// smem: Q[16K] | buf{K 16K, V 32K} x2 = 112 KB
// ---------------------------------------------------------------------------
#define SM_Q      0
#define SM_K(bf)  (16384 + (bf) * 49152)
#define SM_V(bf)  (SM_K(bf) + 16384)
#define SM_TOTAL  (16384 + 2 * 49152)
#define EB(bf)    (16384 + (bf) * 32768)     // each: hi 16KB | lo 16KB

__device__ __forceinline__ void issue_kv(uint32_t sb, int bf, int b, int j0, int tid)
{
    const uint32_t kb = sb + SM_K(bf), vb = sb + SM_V(bf);
    #pragma unroll
    for (int p = 0; p < 4; p++) {
        int idx = p * 256 + tid;
        int r = idx >> 3, c = idx & 7;
        cpa16(sw128(kb, r, c), g_khl + ((size_t)(b * 4096 + j0 + r)) * 64 + c * 8);
    }
    #pragma unroll
    for (int p = 0; p < 8; p++) {
        int idx = p * 256 + tid;
        int r = idx >> 4, c = idx & 15;
        cpa16(sw256(vb, r, c), g_vt + ((size_t)(b * 128 + r)) * 4096 + j0 + c * 8);
    }
}

__device__ __forceinline__ void issue_B(uint32_t sb, int bf, int nh, int ks, int tid)
{
    const uint32_t bh = sb + EB(bf), bl = sb + EB(bf) + 16384;
    #pragma unroll
    for (int p = 0; p < 2; p++) {
        int idx = p * 256 + tid;
        int r = idx >> 2, c = idx & 3;
        const size_t src = (size_t)(nh * 128 + r) * 128 + ks * 32 + c * 8;
        cpa16(sw64(bh, r, c), g_wot_h + src);
        cpa16(sw64(bl, r, c), g_wot_l + src);
    }
}

__device__ __forceinline__ void softmax_chunk(
    const float s[4][4], float& m0, float& m1,
    float& corr0, float& corr1, uint32_t pf[2][4])
{
    float cm0 = -1e30f, cm1 = -1e30f;
    #pragma unroll
    for (int jj = 0; jj < 4; jj++) {
        cm0 = fmaxf(cm0, fmaxf(s[jj][0], s[jj][1]));
        cm1 = fmaxf(cm1, fmaxf(s[jj][2], s[jj][3]));
    }
    cm0 = fmaxf(cm0, __shfl_xor_sync(0xffffffffu, cm0, 1));
    cm0 = fmaxf(cm0, __shfl_xor_sync(0xffffffffu, cm0, 2));
    cm1 = fmaxf(cm1, __shfl_xor_sync(0xffffffffu, cm1, 1));
    cm1 = fmaxf(cm1, __shfl_xor_sync(0xffffffffu, cm1, 2));
    const float mn0 = fmaxf(m0, cm0), mn1 = fmaxf(m1, cm1);
    corr0 = ex2f((m0 - mn0) * L2E);
    corr1 = ex2f((m1 - mn1) * L2E);
    m0 = mn0; m1 = mn1;
    const float sh0 = mn0 * L2E, sh1 = mn1 * L2E;
    #pragma unroll
    for (int jj = 0; jj < 4; jj++) {
        float x0 = fmaf(s[jj][0], L2E, -sh0);
        float x1 = fmaf(s[jj][1], L2E, -sh0);
        float x2 = fmaf(s[jj][2], L2E, -sh1);
        float x3 = fmaf(s[jj][3], L2E, -sh1);
        pf[jj >> 1][(jj & 1) * 2 + 0] = ex2h2(pack_hf(x0, x1));
        pf[jj >> 1][(jj & 1) * 2 + 1] = ex2h2(pack_hf(x2, x3));
    }
}

__global__ __launch_bounds__(256, 1) void attn_kernel(
    const float* __restrict__ x, const float* __restrict__ bo,
    float* __restrict__ out)
{
    extern __shared__ char smc[];
    const uint32_t sb = smem_u32(smc);
    const int tid  = threadIdx.x;
    const int warp = tid >> 5;
    const int lane = tid & 31;
    const int b  = blockIdx.x >> 5;
    const int mt = blockIdx.x & 31;
    const size_t qrow0 = (size_t)b * 4096 + (size_t)mt * 128;
    const int r0 = warp * 16;

    #pragma unroll
    for (int p = 0; p < 4; p++) {
        int idx = p * 256 + tid;
        int r = idx >> 3, c = idx & 7;
        cpa16(sw128(sb + SM_Q, r, c), g_qhl + (qrow0 + r) * 64 + c * 8);
    }
    issue_kv(sb, 0, b, 0, tid);
    cpa_commit(); cpa_wait0(); __syncthreads();

    const int arow = r0 + (lane & 7) + ((lane & 8) ? 8 : 0);
    const int asel = (lane & 16) ? 1 : 0;
    uint32_t qh[2][4], ql[2][4];
    #pragma unroll
    for (int kc = 0; kc < 2; kc++) {
        ldsm4(qh[kc][0], qh[kc][1], qh[kc][2], qh[kc][3],
              sw128(sb + SM_Q, arow, kc * 2 + asel));
        ldsm4(ql[kc][0], ql[kc][1], ql[kc][2], ql[kc][3],
              sw128(sb + SM_Q, arow, 4 + kc * 2 + asel));
    }

    float o[16][4];
    #pragma unroll
    for (int j = 0; j < 16; j++)
        #pragma unroll
        for (int q = 0; q < 4; q++) o[j][q] = 0.f;
    float o16[4] = {0.f, 0.f, 0.f, 0.f};
    float m0 = -1e30f, m1 = -1e30f;

    const uint32_t bones = (lane < 4) ? pack_hf(1.f, 1.f) : 0u;
    const int brow = lane & 7;
    const int bsel = lane >> 3;

    for (int i = 0; i < 32; i++) {
        const int cur = i & 1;
        if (i + 1 < 32) { issue_kv(sb, cur ^ 1, b, (i + 1) * 128, tid); cpa_commit(); }

        const uint32_t kb = sb + SM_K(cur);
        const uint32_t vbuf = sb + SM_V(cur);

        #pragma unroll
        for (int c2k = 0; c2k < 4; c2k++) {
            float s[4][4];
            #pragma unroll
            for (int jj = 0; jj < 4; jj++) {
                const int jt = c2k * 4 + jj;
                s[jj][0] = s[jj][1] = s[jj][2] = s[jj][3] = 0.f;
                uint32_t kr[4], kl[4];
                ldsm4(kr[0], kr[1], kr[2], kr[3], sw128(kb, jt * 8 + brow, bsel));
                ldsm4(kl[0], kl[1], kl[2], kl[3], sw128(kb, jt * 8 + brow, 4 + bsel));
                mma16816(s[jj], qh[0], kr[0], kr[1]);
                mma16816(s[jj], qh[1], kr[2], kr[3]);
                mma16816(s[jj], ql[0], kr[0], kr[1]);
                mma16816(s[jj], ql[1], kr[2], kr[3]);
                mma16816(s[jj], qh[0], kl[0], kl[1]);
                mma16816(s[jj], qh[1], kl[2], kl[3]);
            }
            uint32_t pf[2][4];
            float corr0, corr1;
            softmax_chunk(s, m0, m1, corr0, corr1, pf);
            if (__any_sync(0xffffffffu, (corr0 < 1.f) || (corr1 < 1.f))) {
                #pragma unroll
                for (int j = 0; j < 16; j++) {
                    o[j][0] *= corr0; o[j][1] *= corr0;
                    o[j][2] *= corr1; o[j][3] *= corr1;
                }
                o16[0] *= corr0; o16[1] *= corr0;
                o16[2] *= corr1; o16[3] *= corr1;
            }
            #pragma unroll
            for (int j = 0; j < 16; j++) {
                uint32_t vb[4];
                ldsm4(vb[0], vb[1], vb[2], vb[3], sw256(vbuf, j * 8 + brow, c2k * 4 + bsel));
                mma16816h(o[j], pf[0], vb[0], vb[1]);
                mma16816h(o[j], pf[1], vb[2], vb[3]);
            }
            mma16816h(o16, pf[0], bones, bones);
            mma16816h(o16, pf[1], bones, bones);
        }
        if (i + 1 < 32) { cpa_wait0(); __syncthreads(); }
    }

    // ================= fused output projection =================
    const float l0 = __shfl_sync(0xffffffffu, o16[0], lane & 0x1C);
    const float l1 = __shfl_sync(0xffffffffu, o16[2], lane & 0x1C);
    const float li0 = 1.f / l0;
    const float li1 = 1.f / l1;

    issue_B(sb, 0, 0, 0, tid);
    cpa_commit();

    uint32_t ahf[8][4], alf[8][4];
    #pragma unroll
    for (int kc = 0; kc < 8; kc++) {
        const int j0 = 2 * kc, j1 = 2 * kc + 1;
        float a00 = o[j0][0] * li0, a01 = o[j0][1] * li0;
        float a02 = o[j0][2] * li1, a03 = o[j0][3] * li1;
        float a10 = o[j1][0] * li0, a11 = o[j1][1] * li0;
        float a12 = o[j1][2] * li1, a13 = o[j1][3] * li1;
        uint32_t h0 = pack_bf(a00, a01), h1 = pack_bf(a02, a03);
        uint32_t h2 = pack_bf(a10, a11), h3 = pack_bf(a12, a13);
        ahf[kc][0] = h0; ahf[kc][1] = h1; ahf[kc][2] = h2; ahf[kc][3] = h3;
        alf[kc][0] = pack_bf(a00 - __uint_as_float(h0 << 16),
                             a01 - __uint_as_float(h0 & 0xFFFF0000u));
        alf[kc][1] = pack_bf(a02 - __uint_as_float(h1 << 16),
                             a03 - __uint_as_float(h1 & 0xFFFF0000u));
        alf[kc][2] = pack_bf(a10 - __uint_as_float(h2 << 16),
                             a11 - __uint_as_float(h2 & 0xFFFF0000u));
        alf[kc][3] = pack_bf(a12 - __uint_as_float(h3 << 16),
                             a13 - __uint_as_float(h3 & 0xFFFF0000u));
    }

    const int g = lane >> 2, c2 = (lane & 3) * 2;
    int buf = 0;
    #pragma unroll
    for (int nh = 0; nh < 2; nh++) {
        float acc[16][4];
        #pragma unroll
        for (int j = 0; j < 16; j++)
            #pragma unroll
            for (int q = 0; q < 4; q++) acc[j][q] = 0.f;

        #pragma unroll
        for (int ks = 0; ks < 4; ks++) {
            cpa_wait0(); __syncthreads();
            const int nstep = nh * 4 + ks + 1;
            if (nstep < 8) {
                issue_B(sb, buf ^ 1, nstep >> 2, nstep & 3, tid);
                cpa_commit();
            }
            const uint32_t bhb = sb + EB(buf), blb = sb + EB(buf) + 16384;
            const uint32_t* a0h = ahf[ks * 2];
            const uint32_t* a1h = ahf[ks * 2 + 1];
            const uint32_t* a0l = alf[ks * 2];
            const uint32_t* a1l = alf[ks * 2 + 1];
            #pragma unroll
            for (int j = 0; j < 16; j++) {
                uint32_t bh[4], bl[4];
                ldsm4(bh[0], bh[1], bh[2], bh[3], sw64(bhb, j * 8 + brow, bsel));
                ldsm4(bl[0], bl[1], bl[2], bl[3], sw64(blb, j * 8 + brow, bsel));
                mma16816(acc[j], a0h, bh[0], bh[1]);
                mma16816(acc[j], a1h, bh[2], bh[3]);
                mma16816(acc[j], a0l, bh[0], bh[1]);
                mma16816(acc[j], a1l, bh[2], bh[3]);
                mma16816(acc[j], a0h, bl[0], bl[1]);
                mma16816(acc[j], a1h, bl[2], bl[3]);
            }
            buf ^= 1;
        }
        #pragma unroll
        for (int j = 0; j < 16; j++) {
            const int col = nh * 128 + j * 8 + c2;
            const float b0 = bo[col], b1 = bo[col + 1];
            #pragma unroll
            for (int half = 0; half < 2; half++) {
                const size_t gr = qrow0 + r0 + g + half * 8;
                float2 xr = *(const float2*)(x + gr * 256 + col);
                float2 r;
                r.x = acc[j][half * 2 + 0] + b0 + xr.x;
                r.y = acc[j][half * 2 + 1] + b1 + xr.y;
                *(float2*)(out + gr * 256 + col) = r;
            }
        }
    }
}

// ---------------------------------------------------------------------------
extern "C" void kernel_launch(void* const* d_in, const int* in_sizes, int n_in,
                              void* d_out, int out_size)
{
    const float* x  = (const float*)d_in[0];
    const float* Wq = (const float*)d_in[1];
    const float* bq = (const float*)d_in[2];
    const float* Wk = (const float*)d_in[3];
    const float* bk = (const float*)d_in[4];
    const float* Wv = (const float*)d_in[5];
    const float* bv = (const float*)d_in[6];
    const float* Wo = (const float*)d_in[7];
    const float* bo = (const float*)d_in[8];
    float* out = (float*)d_out;

    cudaFuncSetAttribute(proj_hmma, cudaFuncAttributeMaxDynamicSharedMemorySize, PJ_SMEM);
    cudaFuncSetAttribute(attn_kernel, cudaFuncAttributeMaxDynamicSharedMemorySize, SM_TOTAL);

    prep_w<<<448, 256>>>(Wq, Wk, Wv, Wo);
    proj_hmma<<<256, 256, PJ_SMEM>>>(x, bq, bk, bv);
    attn_kernel<<<256, 256, SM_TOTAL>>>(x, bo, out);
}